// round 16
// baseline (speedup 1.0000x reference)
#include <cuda_runtime.h>
#include <cuda_fp16.h>
#include <math.h>
#include <stdint.h>

// Problem constants
#define B_   2
#define S_   2048
#define E_   2048
#define H_   16
#define HS_  128
#define M_   (B_ * S_)      // 4096
#define NQKV (3 * E_)       // 6144
#define KDIM E_             // 2048
#define ROT_ 32
#define QSCALE 0.08838834764831845f   // 1/sqrt(128)

// Scratch (device globals; fp16 storage, fp32 accumulate)
__device__ __align__(16) __half g_Qh[(size_t)B_ * H_ * S_ * HS_];  // [bh][s][d], pre-scaled
__device__ __align__(16) __half g_Kh[(size_t)B_ * H_ * S_ * HS_];  // [bh][s][d]
__device__ __align__(16) __half g_Vt[(size_t)B_ * H_ * HS_ * S_];  // [bh][d][s]  (transposed!)
__device__ __align__(16) __half g_Yh[(size_t)M_ * E_];             // flash output
__device__ __align__(16) __half g_Xh[(size_t)M_ * E_];
__device__ __align__(16) __half g_Wqh[(size_t)NQKV * E_];
__device__ __align__(16) __half g_Wdh[(size_t)E_ * E_];

// ---------------------------------------------------------------------------
// Helpers
// ---------------------------------------------------------------------------
__device__ __forceinline__ uint32_t smem_to_u32(const void* p) {
    uint32_t a;
    asm("{ .reg .u64 t; cvta.to.shared.u64 t, %1; cvt.u32.u64 %0, t; }"
        : "=r"(a) : "l"(p));
    return a;
}

__device__ __forceinline__ void cp_async16(uint32_t dst, const void* src) {
    asm volatile("cp.async.cg.shared.global [%0], [%1], 16;" :: "r"(dst), "l"(src));
}
#define CP_COMMIT() asm volatile("cp.async.commit_group;" ::: "memory")
template <int N>
__device__ __forceinline__ void cp_wait() {
    asm volatile("cp.async.wait_group %0;" :: "n"(N) : "memory");
}

// mma.sync m16n8k16 fp16 in / fp32 accum
__device__ __forceinline__ void mma_f16(float* d, const uint32_t* a, const uint32_t* b) {
    asm volatile(
        "mma.sync.aligned.m16n8k16.row.col.f32.f16.f16.f32 "
        "{%0,%1,%2,%3}, {%4,%5,%6,%7}, {%8,%9}, {%0,%1,%2,%3};"
        : "+f"(d[0]), "+f"(d[1]), "+f"(d[2]), "+f"(d[3])
        : "r"(a[0]), "r"(a[1]), "r"(a[2]), "r"(a[3]), "r"(b[0]), "r"(b[1]));
}

// ldmatrix x4: four 8x8 b16 tiles -> 4 regs
__device__ __forceinline__ void ldsm_x4(uint32_t* r, uint32_t addr) {
    asm volatile("ldmatrix.sync.aligned.m8n8.x4.shared.b16 {%0,%1,%2,%3}, [%4];"
        : "=r"(r[0]), "=r"(r[1]), "=r"(r[2]), "=r"(r[3]) : "r"(addr));
}

// ---------------------------------------------------------------------------
// Convert fp32 -> fp16 (RN); which: 0 -> g_Xh, 1 -> g_Wqh, 2 -> g_Wdh
// ---------------------------------------------------------------------------
__global__ __launch_bounds__(256) void convert_kernel(const float* __restrict__ src,
                                                      int which, int n8)
{
    __half* dst = (which == 0) ? g_Xh : (which == 1) ? g_Wqh : g_Wdh;
    int i = blockIdx.x * blockDim.x + threadIdx.x;
    if (i >= n8) return;
    float4 u = ((const float4*)src)[(size_t)i * 2];
    float4 v = ((const float4*)src)[(size_t)i * 2 + 1];
    __half2 h0 = __floats2half2_rn(u.x, u.y);
    __half2 h1 = __floats2half2_rn(u.z, u.w);
    __half2 h2 = __floats2half2_rn(v.x, v.y);
    __half2 h3 = __floats2half2_rn(v.z, v.w);
    uint4 o;
    o.x = *(uint32_t*)&h0; o.y = *(uint32_t*)&h1;
    o.z = *(uint32_t*)&h2; o.w = *(uint32_t*)&h3;
    *(uint4*)(dst + (size_t)i * 8) = o;
}

// ---------------------------------------------------------------------------
// fp16 mma GEMM (unchanged from R14/15): CTA 128x128, BK=64, ldmatrix frags,
// 3-stage single-sync cp.async pipeline, 2 CTA/SM.
// ---------------------------------------------------------------------------
#define GROWH 72
#define STG_H (128 * GROWH)
#define NSTG 3
#define GEMM_SMEM (2 * NSTG * STG_H * 2)  // 110592 bytes
#define KCH (KDIM / 64)                   // 32

__device__ __forceinline__ void scatter_qkv2(int m, int n, float v0, float v1) {
    int b = m >> 11;
    int srow = m & (S_ - 1);
    int h = n / 384;
    int c = n % 384;
    int bh = b * H_ + h;
    if (c < HS_) {
        size_t base = ((size_t)bh * S_ + srow) * HS_ + c;
        *(__half2*)&g_Qh[base] = __floats2half2_rn(v0 * QSCALE, v1 * QSCALE);
    } else if (c < 2 * HS_) {
        size_t base = ((size_t)bh * S_ + srow) * HS_ + (c - HS_);
        *(__half2*)&g_Kh[base] = __floats2half2_rn(v0, v1);
    } else {
        int dd = c - 2 * HS_;
        size_t tb = ((size_t)bh * HS_ + dd) * S_ + srow;   // transposed [d][s]
        g_Vt[tb]      = __float2half_rn(v0);
        g_Vt[tb + S_] = __float2half_rn(v1);
    }
}

template <int MODE>
__global__ __launch_bounds__(256, 2) void mma_gemm(
    const float* __restrict__ bias, float* __restrict__ C)
{
    extern __shared__ __half smh[];
    __half* As = smh;
    __half* Bs = smh + NSTG * STG_H;
    const uint32_t aAddr = smem_to_u32(As);
    const uint32_t bAddr = smem_to_u32(Bs);

    const int tid  = threadIdx.x;
    const int wid  = tid >> 5;
    const int lane = tid & 31;
    const int g    = lane >> 2;
    const int q    = lane & 3;
    const int wm   = wid & 1;
    const int wn   = wid >> 1;
    const int mBase = blockIdx.y * 128;
    const int nBase = blockIdx.x * 128;

    const __half* Ag = (MODE == 0) ? g_Xh : g_Yh;
    const __half* Wg = (MODE == 0) ? g_Wqh : g_Wdh;

    uint32_t aOff[4], bOff[2];
    {
        int am = wm * 64 + (lane & 15);
        int ak = (lane >> 4) * 8;
        #pragma unroll
        for (int mt = 0; mt < 4; mt++)
            aOff[mt] = (uint32_t)(((am + mt * 16) * GROWH + ak) * 2);
        int bk = ((lane >> 3) & 1) * 8;
        int bn = wn * 32 + ((lane >> 4) * 8) + (lane & 7);
        #pragma unroll
        for (int p = 0; p < 2; p++)
            bOff[p] = (uint32_t)(((bn + p * 16) * GROWH + bk) * 2);
    }

    float d[4][4][4];
    #pragma unroll
    for (int mt = 0; mt < 4; mt++)
        #pragma unroll
        for (int nt = 0; nt < 4; nt++)
            #pragma unroll
            for (int r = 0; r < 4; r++) d[mt][nt][r] = 0.f;

    auto load_stage = [&](int km) {
        int buf = km % NSTG;
        uint32_t ad = aAddr + buf * (STG_H * 2);
        uint32_t bd = bAddr + buf * (STG_H * 2);
        const __half* ap = Ag + (size_t)mBase * KDIM + km * 64;
        const __half* wp = Wg + (size_t)nBase * KDIM + km * 64;
        #pragma unroll
        for (int t = 0; t < 4; t++) {
            int f4 = t * 256 + tid;
            int r = f4 >> 3, c = f4 & 7;
            cp_async16(ad + r * (GROWH * 2) + c * 16, ap + (size_t)r * KDIM + c * 8);
            cp_async16(bd + r * (GROWH * 2) + c * 16, wp + (size_t)r * KDIM + c * 8);
        }
        CP_COMMIT();
    };

    load_stage(0);
    load_stage(1);

    for (int km = 0; km < KCH; km++) {
        if (km + 2 <= KCH - 1) cp_wait<1>();
        else                   cp_wait<0>();
        __syncthreads();

        if (km + 2 < KCH) load_stage(km + 2);

        int buf = km % NSTG;
        uint32_t aB = aAddr + buf * (STG_H * 2);
        uint32_t bB = bAddr + buf * (STG_H * 2);
        #pragma unroll
        for (int kk = 0; kk < 4; kk++) {
            uint32_t kadd = kk * 32;
            uint32_t a[4][4], bq[2][4];
            #pragma unroll
            for (int mt = 0; mt < 4; mt++)
                ldsm_x4(a[mt], aB + aOff[mt] + kadd);
            #pragma unroll
            for (int p = 0; p < 2; p++)
                ldsm_x4(bq[p], bB + bOff[p] + kadd);
            #pragma unroll
            for (int mt = 0; mt < 4; mt++) {
                mma_f16(d[mt][0], a[mt], &bq[0][0]);
                mma_f16(d[mt][1], a[mt], &bq[0][2]);
                mma_f16(d[mt][2], a[mt], &bq[1][0]);
                mma_f16(d[mt][3], a[mt], &bq[1][2]);
            }
        }
    }

    #pragma unroll
    for (int mt = 0; mt < 4; mt++) {
        int m0 = mBase + wm * 64 + mt * 16 + g;
        #pragma unroll
        for (int nt = 0; nt < 4; nt++) {
            int n0 = nBase + wn * 32 + nt * 8 + 2 * q;
            float2 bb = *(const float2*)&bias[n0];
            float v0 = d[mt][nt][0] + bb.x;
            float v1 = d[mt][nt][1] + bb.y;
            float v2 = d[mt][nt][2] + bb.x;
            float v3 = d[mt][nt][3] + bb.y;
            if (MODE == 0) {
                scatter_qkv2(m0,     n0, v0, v1);
                scatter_qkv2(m0 + 8, n0, v2, v3);
            } else {
                *(float2*)&C[(size_t)m0 * E_ + n0]       = make_float2(v0, v1);
                *(float2*)&C[(size_t)(m0 + 8) * E_ + n0] = make_float2(v2, v3);
            }
        }
    }
}

// ---------------------------------------------------------------------------
// RoPE on half Q/K: rotate first ROT=32 dims; fp32 math, RN back to half.
// ---------------------------------------------------------------------------
__global__ __launch_bounds__(256) void rope_kernel()
{
    int idx = blockIdx.x * blockDim.x + threadIdx.x;
    if (idx >= B_ * H_ * S_ * (ROT_ / 2)) return;
    int j  = idx & 15;
    int s  = (idx >> 4) & (S_ - 1);
    int bh = idx >> 15;

    float inv = powf(10000.0f, -((float)j) / 16.0f);
    float ang = (float)s * inv;
    float c  = cosf(ang);
    float sn = sinf(ang);

    size_t base = ((size_t)bh * S_ + s) * HS_;
    __half* qp = &g_Qh[base];
    __half* kp = &g_Kh[base];

    float q0 = __half2float(qp[j]), q1 = __half2float(qp[j + 16]);
    qp[j]      = __float2half_rn(q0 * c - q1 * sn);
    qp[j + 16] = __float2half_rn(q1 * c + q0 * sn);

    float k0 = __half2float(kp[j]), k1 = __half2float(kp[j + 16]);
    kp[j]      = __float2half_rn(k0 * c - k1 * sn);
    kp[j + 16] = __float2half_rn(k1 * c + k0 * sn);
}

// ---------------------------------------------------------------------------
// Flash attention fp16 + ldmatrix; NOW 2 CTAs/SM (launch_bounds(256,2)) so one
// CTA's softmax/barrier bubbles overlap the other's mma stream.
// 90112 B smem/CTA x2 = 176 KB <= 228 KB; 128 regs/thread cap.
// ---------------------------------------------------------------------------
#define FQ 128
#define FKV 64
#define QSTRH 136
#define PSTRH 72
#define VSTRH 72
#define FH_K (FQ * QSTRH)                 // 17408
#define FH_V (FH_K + FKV * QSTRH)         // 26112
#define FH_P (FH_V + HS_ * VSTRH)         // 35328
#define FB_A ((FH_P + FQ * PSTRH) * 2)    // 89088 bytes
#define FB_L (FB_A + FQ * 4)              // 89600
#define FLASH_SMEM (FB_L + FQ * 4)        // 90112 bytes

__global__ __launch_bounds__(256, 2) void flash3_kernel()
{
    extern __shared__ char smc[];
    __half* Qs = (__half*)smc;
    __half* Ks = (__half*)smc + FH_K;
    __half* Vs = (__half*)smc + FH_V;
    __half* Ps = (__half*)smc + FH_P;
    float*  Al = (float*)(smc + FB_A);
    float*  Ll = (float*)(smc + FB_L);
    const uint32_t sQ = smem_to_u32(Qs);
    const uint32_t sK = smem_to_u32(Ks);
    const uint32_t sV = smem_to_u32(Vs);
    const uint32_t sP = smem_to_u32(Ps);

    const int tid  = threadIdx.x;
    const int wid  = tid >> 5;
    const int lane = tid & 31;
    const int g = lane >> 2, q = lane & 3;
    const int bh = blockIdx.y;
    const int qt = gridDim.x - 1 - blockIdx.x;
    const int qBase = qt * FQ;
    const int wm = wid & 1, wn = wid >> 1;

    const __half* Qg  = g_Qh + ((size_t)bh * S_ + qBase) * HS_;
    const __half* Kg  = g_Kh + (size_t)bh * S_ * HS_;
    const __half* Vtg = g_Vt + (size_t)bh * HS_ * S_;

    // ldmatrix lane-address offsets (bytes)
    const uint32_t qOff =
        (uint32_t)(((wid * 16 + (lane & 15)) * QSTRH + (lane >> 4) * 8) * 2);
    uint32_t kOff[4];
    {
        int bk = ((lane >> 3) & 1) * 8;
        int bn = ((lane >> 4) * 8) + (lane & 7);
        #pragma unroll
        for (int j = 0; j < 4; j++)
            kOff[j] = (uint32_t)(((j * 16 + bn) * QSTRH + bk) * 2);
    }
    uint32_t pOff[4];
    {
        int pm = wm * 64 + (lane & 15);
        int pk = (lane >> 4) * 8;
        #pragma unroll
        for (int mt = 0; mt < 4; mt++)
            pOff[mt] = (uint32_t)(((pm + mt * 16) * PSTRH + pk) * 2);
    }
    uint32_t vOff[2];
    {
        int bk = ((lane >> 3) & 1) * 8;
        int bn = wn * 32 + ((lane >> 4) * 8) + (lane & 7);
        #pragma unroll
        for (int p = 0; p < 2; p++)
            vOff[p] = (uint32_t)(((bn + p * 16) * VSTRH + bk) * 2);
    }

    // prologue: Q (128 rows x 256B) + K tile 0 (64 rows x 256B)
    #pragma unroll
    for (int i = 0; i < 8; i++) {
        int f4 = i * 256 + tid;
        int r = f4 >> 4, c = f4 & 15;
        cp_async16(sQ + r * (QSTRH * 2) + c * 16, Qg + r * HS_ + c * 8);
    }
    #pragma unroll
    for (int i = 0; i < 4; i++) {
        int f4 = i * 256 + tid;
        int r = f4 >> 4, c = f4 & 15;
        cp_async16(sK + r * (QSTRH * 2) + c * 16, Kg + r * HS_ + c * 8);
    }
    CP_COMMIT();

    float m0 = -1e30f, m1 = -1e30f, l0 = 0.f, l1 = 0.f;
    float o[4][4][4];
    #pragma unroll
    for (int mt = 0; mt < 4; mt++)
        #pragma unroll
        for (int nt = 0; nt < 4; nt++)
            #pragma unroll
            for (int r = 0; r < 4; r++) o[mt][nt][r] = 0.f;

    const int srow0 = wid * 16 + g;
    const int ntiles = 2 * qt + 2;

    for (int t = 0; t < ntiles; t++) {
        cp_wait<0>();
        __syncthreads();

        // prefetch V^T(t) — covered by S phase
        #pragma unroll
        for (int i = 0; i < 4; i++) {
            int f4 = i * 256 + tid;
            int r = f4 >> 3, c = f4 & 7;
            cp_async16(sV + r * (VSTRH * 2) + c * 16,
                       Vtg + (size_t)r * S_ + t * FKV + c * 8);
        }
        CP_COMMIT();

        // ---- S = Q K^T via ldmatrix ----
        float s[8][4];
        #pragma unroll
        for (int nt = 0; nt < 8; nt++)
            #pragma unroll
            for (int r = 0; r < 4; r++) s[nt][r] = 0.f;

        #pragma unroll
        for (int kk = 0; kk < 8; kk++) {
            uint32_t kadd = kk * 32;
            uint32_t a[4];
            ldsm_x4(a, sQ + qOff + kadd);
            #pragma unroll
            for (int j = 0; j < 4; j++) {
                uint32_t bq[4];
                ldsm_x4(bq, sK + kOff[j] + kadd);
                mma_f16(s[2 * j],     a, &bq[0]);
                mma_f16(s[2 * j + 1], a, &bq[2]);
            }
        }

        // ---- causal mask (diagonal tiles) ----
        if (t >= 2 * qt) {
            int r0 = qBase + srow0, r1 = r0 + 8;
            #pragma unroll
            for (int nt = 0; nt < 8; nt++) {
                int c0 = t * FKV + nt * 8 + 2 * q;
                if (c0     > r0) s[nt][0] = -1e30f;
                if (c0 + 1 > r0) s[nt][1] = -1e30f;
                if (c0     > r1) s[nt][2] = -1e30f;
                if (c0 + 1 > r1) s[nt][3] = -1e30f;
            }
        }

        // ---- online softmax (rows srow0, srow0+8; quad reduce) ----
        float rm0 = -1e30f, rm1 = -1e30f;
        #pragma unroll
        for (int nt = 0; nt < 8; nt++) {
            rm0 = fmaxf(rm0, fmaxf(s[nt][0], s[nt][1]));
            rm1 = fmaxf(rm1, fmaxf(s[nt][2], s[nt][3]));
        }
        rm0 = fmaxf(rm0, __shfl_xor_sync(0xffffffffu, rm0, 1));
        rm0 = fmaxf(rm0, __shfl_xor_sync(0xffffffffu, rm0, 2));
        rm1 = fmaxf(rm1, __shfl_xor_sync(0xffffffffu, rm1, 1));
        rm1 = fmaxf(rm1, __shfl_xor_sync(0xffffffffu, rm1, 2));
        float mn0 = fmaxf(m0, rm0), mn1 = fmaxf(m1, rm1);
        float al0 = __expf(m0 - mn0), al1 = __expf(m1 - mn1);
        float rs0 = 0.f, rs1 = 0.f;
        #pragma unroll
        for (int nt = 0; nt < 8; nt++) {
            float p0 = __expf(s[nt][0] - mn0);
            float p1 = __expf(s[nt][1] - mn0);
            float p2 = __expf(s[nt][2] - mn1);
            float p3 = __expf(s[nt][3] - mn1);
            rs0 += p0 + p1;
            rs1 += p2 + p3;
            int cl = nt * 8 + 2 * q;
            *(__half2*)&Ps[(size_t)srow0 * PSTRH + cl]       = __floats2half2_rn(p0, p1);
            *(__half2*)&Ps[(size_t)(srow0 + 8) * PSTRH + cl] = __floats2half2_rn(p2, p3);
        }
        rs0 += __shfl_xor_sync(0xffffffffu, rs0, 1);
        rs0 += __shfl_xor_sync(0xffffffffu, rs0, 2);
        rs1 += __shfl_xor_sync(0xffffffffu, rs1, 1);
        rs1 += __shfl_xor_sync(0xffffffffu, rs1, 2);
        l0 = l0 * al0 + rs0;
        l1 = l1 * al1 + rs1;
        m0 = mn0; m1 = mn1;
        if (q == 0) { Al[srow0] = al0; Al[srow0 + 8] = al1; }

        cp_wait<0>();             // V^T(t) arrived
        __syncthreads();          // Ps/Al visible; K buffer free

        // prefetch K(t+1) — covered by PV phase
        if (t + 1 < ntiles) {
            const __half* Kt = Kg + (size_t)(t + 1) * FKV * HS_;
            #pragma unroll
            for (int i = 0; i < 4; i++) {
                int f4 = i * 256 + tid;
                int r = f4 >> 4, c = f4 & 15;
                cp_async16(sK + r * (QSTRH * 2) + c * 16, Kt + r * HS_ + c * 8);
            }
            CP_COMMIT();
        }

        // ---- O rescale + O += P V via ldmatrix ----
        #pragma unroll
        for (int mt = 0; mt < 4; mt++) {
            float a0 = Al[wm * 64 + mt * 16 + g];
            float a1 = Al[wm * 64 + mt * 16 + g + 8];
            #pragma unroll
            for (int nt = 0; nt < 4; nt++) {
                o[mt][nt][0] *= a0; o[mt][nt][1] *= a0;
                o[mt][nt][2] *= a1; o[mt][nt][3] *= a1;
            }
        }
        #pragma unroll
        for (int kk = 0; kk < 4; kk++) {
            uint32_t kadd = kk * 32;
            uint32_t pa[4][4], bv[2][4];
            #pragma unroll
            for (int mt = 0; mt < 4; mt++)
                ldsm_x4(pa[mt], sP + pOff[mt] + kadd);
            #pragma unroll
            for (int p = 0; p < 2; p++)
                ldsm_x4(bv[p], sV + vOff[p] + kadd);
            #pragma unroll
            for (int mt = 0; mt < 4; mt++) {
                mma_f16(o[mt][0], pa[mt], &bv[0][0]);
                mma_f16(o[mt][1], pa[mt], &bv[0][2]);
                mma_f16(o[mt][2], pa[mt], &bv[1][0]);
                mma_f16(o[mt][3], pa[mt], &bv[1][2]);
            }
        }
    }

    // ---- writeout: normalize, RN to half, store g_Yh [B,S,E] ----
    if (q == 0) { Ll[srow0] = l0; Ll[srow0 + 8] = l1; }
    __syncthreads();
    int b = bh >> 4, h = bh & 15;
    #pragma unroll
    for (int mt = 0; mt < 4; mt++) {
        int r0 = wm * 64 + mt * 16 + g;
        float i0 = 1.f / Ll[r0];
        float i1 = 1.f / Ll[r0 + 8];
        __half* Y0 = g_Yh + ((size_t)b * S_ + qBase + r0) * E_ + h * HS_;
        __half* Y1 = Y0 + 8 * E_;
        #pragma unroll
        for (int nt = 0; nt < 4; nt++) {
            int c0 = wn * 32 + nt * 8 + 2 * q;
            *(__half2*)&Y0[c0] = __floats2half2_rn(o[mt][nt][0] * i0, o[mt][nt][1] * i0);
            *(__half2*)&Y1[c0] = __floats2half2_rn(o[mt][nt][2] * i1, o[mt][nt][3] * i1);
        }
    }
}

// ---------------------------------------------------------------------------
// Launch
// ---------------------------------------------------------------------------
extern "C" void kernel_launch(void* const* d_in, const int* in_sizes, int n_in,
                              void* d_out, int out_size)
{
    const float* x       = (const float*)d_in[0];
    const float* w_qkv   = (const float*)d_in[1];
    const float* b_qkv   = (const float*)d_in[2];
    const float* w_dense = (const float*)d_in[3];
    const float* b_dense = (const float*)d_in[4];
    float* out = (float*)d_out;

    cudaFuncSetAttribute(mma_gemm<0>, cudaFuncAttributeMaxDynamicSharedMemorySize, GEMM_SMEM);
    cudaFuncSetAttribute(mma_gemm<1>, cudaFuncAttributeMaxDynamicSharedMemorySize, GEMM_SMEM);
    cudaFuncSetAttribute(flash3_kernel, cudaFuncAttributeMaxDynamicSharedMemorySize, FLASH_SMEM);

    // 0. Convert GEMM inputs to fp16 (RN)
    convert_kernel<<<(M_ * E_ / 8 + 255) / 256, 256>>>(x, 0, M_ * E_ / 8);
    convert_kernel<<<(NQKV * E_ / 8 + 255) / 256, 256>>>(w_qkv, 1, NQKV * E_ / 8);
    convert_kernel<<<(E_ * E_ / 8 + 255) / 256, 256>>>(w_dense, 2, E_ * E_ / 8);

    // 1. QKV projection + bias -> Qh (scaled) / Kh / V^T (all fp16)
    mma_gemm<0><<<dim3(NQKV / 128, M_ / 128), 256, GEMM_SMEM>>>(b_qkv, nullptr);

    // 2. RoPE on first 32 dims of Q and K
    rope_kernel<<<(B_ * H_ * S_ * (ROT_ / 2)) / 256, 256>>>();

    // 3. Causal flash attention (fp16 mma + ldmatrix, 2 CTA/SM) -> g_Yh
    flash3_kernel<<<dim3(S_ / FQ, B_ * H_), 256, FLASH_SMEM>>>();

    // 4. Dense projection + bias -> fp32 output
    mma_gemm<1><<<dim3(E_ / 128, M_ / 128), 256, GEMM_SMEM>>>(b_dense, out);
}

// round 17
// speedup vs baseline: 1.0310x; 1.0310x over previous
#include <cuda_runtime.h>
#include <cuda_fp16.h>
#include <math.h>
#include <stdint.h>

// Problem constants
#define B_   2
#define S_   2048
#define E_   2048
#define H_   16
#define HS_  128
#define M_   (B_ * S_)      // 4096
#define NQKV (3 * E_)       // 6144
#define KDIM E_             // 2048
#define ROT_ 32
#define QSCALE 0.08838834764831845f   // 1/sqrt(128)

// Scratch (device globals; fp16 storage, fp32 accumulate)
__device__ __align__(16) __half g_Qh[(size_t)B_ * H_ * S_ * HS_];  // [bh][s][d], pre-scaled
__device__ __align__(16) __half g_Kh[(size_t)B_ * H_ * S_ * HS_];  // [bh][s][d]
__device__ __align__(16) __half g_Vt[(size_t)B_ * H_ * HS_ * S_];  // [bh][d][s]  (transposed!)
__device__ __align__(16) __half g_Yh[(size_t)M_ * E_];             // flash output
__device__ __align__(16) __half g_Xh[(size_t)M_ * E_];
__device__ __align__(16) __half g_Wqh[(size_t)NQKV * E_];
__device__ __align__(16) __half g_Wdh[(size_t)E_ * E_];

// ---------------------------------------------------------------------------
// Helpers
// ---------------------------------------------------------------------------
__device__ __forceinline__ uint32_t smem_to_u32(const void* p) {
    uint32_t a;
    asm("{ .reg .u64 t; cvta.to.shared.u64 t, %1; cvt.u32.u64 %0, t; }"
        : "=r"(a) : "l"(p));
    return a;
}

__device__ __forceinline__ void cp_async16(uint32_t dst, const void* src) {
    asm volatile("cp.async.cg.shared.global [%0], [%1], 16;" :: "r"(dst), "l"(src));
}
#define CP_COMMIT() asm volatile("cp.async.commit_group;" ::: "memory")
template <int N>
__device__ __forceinline__ void cp_wait() {
    asm volatile("cp.async.wait_group %0;" :: "n"(N) : "memory");
}

// mma.sync m16n8k16 fp16 in / fp32 accum
__device__ __forceinline__ void mma_f16(float* d, const uint32_t* a, const uint32_t* b) {
    asm volatile(
        "mma.sync.aligned.m16n8k16.row.col.f32.f16.f16.f32 "
        "{%0,%1,%2,%3}, {%4,%5,%6,%7}, {%8,%9}, {%0,%1,%2,%3};"
        : "+f"(d[0]), "+f"(d[1]), "+f"(d[2]), "+f"(d[3])
        : "r"(a[0]), "r"(a[1]), "r"(a[2]), "r"(a[3]), "r"(b[0]), "r"(b[1]));
}

// ldmatrix x4: four 8x8 b16 tiles -> 4 regs
__device__ __forceinline__ void ldsm_x4(uint32_t* r, uint32_t addr) {
    asm volatile("ldmatrix.sync.aligned.m8n8.x4.shared.b16 {%0,%1,%2,%3}, [%4];"
        : "=r"(r[0]), "=r"(r[1]), "=r"(r[2]), "=r"(r[3]) : "r"(addr));
}

// ---------------------------------------------------------------------------
// Convert fp32 -> fp16 (RN); single fused launch for x, w_qkv, w_dense
// ---------------------------------------------------------------------------
#define N8_X   (M_ * E_ / 8)       // 1048576
#define N8_WQ  (NQKV * E_ / 8)     // 1572864
#define N8_WD  (E_ * E_ / 8)       // 524288
#define N8_ALL (N8_X + N8_WQ + N8_WD)

__global__ __launch_bounds__(256) void convert_all_kernel(
    const float* __restrict__ x, const float* __restrict__ wq,
    const float* __restrict__ wd)
{
    int i = blockIdx.x * blockDim.x + threadIdx.x;
    if (i >= N8_ALL) return;
    const float* src;
    __half* dst;
    int j;
    if (i < N8_X)              { src = x;  dst = g_Xh;  j = i; }
    else if (i < N8_X + N8_WQ) { src = wq; dst = g_Wqh; j = i - N8_X; }
    else                       { src = wd; dst = g_Wdh; j = i - N8_X - N8_WQ; }
    float4 u = ((const float4*)src)[(size_t)j * 2];
    float4 v = ((const float4*)src)[(size_t)j * 2 + 1];
    __half2 h0 = __floats2half2_rn(u.x, u.y);
    __half2 h1 = __floats2half2_rn(u.z, u.w);
    __half2 h2 = __floats2half2_rn(v.x, v.y);
    __half2 h3 = __floats2half2_rn(v.z, v.w);
    uint4 o;
    o.x = *(uint32_t*)&h0; o.y = *(uint32_t*)&h1;
    o.z = *(uint32_t*)&h2; o.w = *(uint32_t*)&h3;
    *(uint4*)(dst + (size_t)j * 8) = o;
}

// ---------------------------------------------------------------------------
// fp16 mma GEMM (unchanged): CTA 128x128, BK=64, ldmatrix frags,
// 3-stage single-sync cp.async pipeline, 2 CTA/SM.
// ---------------------------------------------------------------------------
#define GROWH 72
#define STG_H (128 * GROWH)
#define NSTG 3
#define GEMM_SMEM (2 * NSTG * STG_H * 2)  // 110592 bytes
#define KCH (KDIM / 64)                   // 32

__device__ __forceinline__ void scatter_qkv2(int m, int n, float v0, float v1) {
    int b = m >> 11;
    int srow = m & (S_ - 1);
    int h = n / 384;
    int c = n % 384;
    int bh = b * H_ + h;
    if (c < HS_) {
        size_t base = ((size_t)bh * S_ + srow) * HS_ + c;
        *(__half2*)&g_Qh[base] = __floats2half2_rn(v0 * QSCALE, v1 * QSCALE);
    } else if (c < 2 * HS_) {
        size_t base = ((size_t)bh * S_ + srow) * HS_ + (c - HS_);
        *(__half2*)&g_Kh[base] = __floats2half2_rn(v0, v1);
    } else {
        int dd = c - 2 * HS_;
        size_t tb = ((size_t)bh * HS_ + dd) * S_ + srow;   // transposed [d][s]
        g_Vt[tb]      = __float2half_rn(v0);
        g_Vt[tb + S_] = __float2half_rn(v1);
    }
}

template <int MODE>
__global__ __launch_bounds__(256, 2) void mma_gemm(
    const float* __restrict__ bias, float* __restrict__ C)
{
    extern __shared__ __half smh[];
    __half* As = smh;
    __half* Bs = smh + NSTG * STG_H;
    const uint32_t aAddr = smem_to_u32(As);
    const uint32_t bAddr = smem_to_u32(Bs);

    const int tid  = threadIdx.x;
    const int wid  = tid >> 5;
    const int lane = tid & 31;
    const int g    = lane >> 2;
    const int q    = lane & 3;
    const int wm   = wid & 1;
    const int wn   = wid >> 1;
    const int mBase = blockIdx.y * 128;
    const int nBase = blockIdx.x * 128;

    const __half* Ag = (MODE == 0) ? g_Xh : g_Yh;
    const __half* Wg = (MODE == 0) ? g_Wqh : g_Wdh;

    uint32_t aOff[4], bOff[2];
    {
        int am = wm * 64 + (lane & 15);
        int ak = (lane >> 4) * 8;
        #pragma unroll
        for (int mt = 0; mt < 4; mt++)
            aOff[mt] = (uint32_t)(((am + mt * 16) * GROWH + ak) * 2);
        int bk = ((lane >> 3) & 1) * 8;
        int bn = wn * 32 + ((lane >> 4) * 8) + (lane & 7);
        #pragma unroll
        for (int p = 0; p < 2; p++)
            bOff[p] = (uint32_t)(((bn + p * 16) * GROWH + bk) * 2);
    }

    float d[4][4][4];
    #pragma unroll
    for (int mt = 0; mt < 4; mt++)
        #pragma unroll
        for (int nt = 0; nt < 4; nt++)
            #pragma unroll
            for (int r = 0; r < 4; r++) d[mt][nt][r] = 0.f;

    auto load_stage = [&](int km) {
        int buf = km % NSTG;
        uint32_t ad = aAddr + buf * (STG_H * 2);
        uint32_t bd = bAddr + buf * (STG_H * 2);
        const __half* ap = Ag + (size_t)mBase * KDIM + km * 64;
        const __half* wp = Wg + (size_t)nBase * KDIM + km * 64;
        #pragma unroll
        for (int t = 0; t < 4; t++) {
            int f4 = t * 256 + tid;
            int r = f4 >> 3, c = f4 & 7;
            cp_async16(ad + r * (GROWH * 2) + c * 16, ap + (size_t)r * KDIM + c * 8);
            cp_async16(bd + r * (GROWH * 2) + c * 16, wp + (size_t)r * KDIM + c * 8);
        }
        CP_COMMIT();
    };

    load_stage(0);
    load_stage(1);

    for (int km = 0; km < KCH; km++) {
        if (km + 2 <= KCH - 1) cp_wait<1>();
        else                   cp_wait<0>();
        __syncthreads();

        if (km + 2 < KCH) load_stage(km + 2);

        int buf = km % NSTG;
        uint32_t aB = aAddr + buf * (STG_H * 2);
        uint32_t bB = bAddr + buf * (STG_H * 2);
        #pragma unroll
        for (int kk = 0; kk < 4; kk++) {
            uint32_t kadd = kk * 32;
            uint32_t a[4][4], bq[2][4];
            #pragma unroll
            for (int mt = 0; mt < 4; mt++)
                ldsm_x4(a[mt], aB + aOff[mt] + kadd);
            #pragma unroll
            for (int p = 0; p < 2; p++)
                ldsm_x4(bq[p], bB + bOff[p] + kadd);
            #pragma unroll
            for (int mt = 0; mt < 4; mt++) {
                mma_f16(d[mt][0], a[mt], &bq[0][0]);
                mma_f16(d[mt][1], a[mt], &bq[0][2]);
                mma_f16(d[mt][2], a[mt], &bq[1][0]);
                mma_f16(d[mt][3], a[mt], &bq[1][2]);
            }
        }
    }

    #pragma unroll
    for (int mt = 0; mt < 4; mt++) {
        int m0 = mBase + wm * 64 + mt * 16 + g;
        #pragma unroll
        for (int nt = 0; nt < 4; nt++) {
            int n0 = nBase + wn * 32 + nt * 8 + 2 * q;
            float2 bb = *(const float2*)&bias[n0];
            float v0 = d[mt][nt][0] + bb.x;
            float v1 = d[mt][nt][1] + bb.y;
            float v2 = d[mt][nt][2] + bb.x;
            float v3 = d[mt][nt][3] + bb.y;
            if (MODE == 0) {
                scatter_qkv2(m0,     n0, v0, v1);
                scatter_qkv2(m0 + 8, n0, v2, v3);
            } else {
                *(float2*)&C[(size_t)m0 * E_ + n0]       = make_float2(v0, v1);
                *(float2*)&C[(size_t)(m0 + 8) * E_ + n0] = make_float2(v2, v3);
            }
        }
    }
}

// ---------------------------------------------------------------------------
// RoPE on half Q/K: rotate first ROT=32 dims; fp32 math, RN back to half.
// ---------------------------------------------------------------------------
__global__ __launch_bounds__(256) void rope_kernel()
{
    int idx = blockIdx.x * blockDim.x + threadIdx.x;
    if (idx >= B_ * H_ * S_ * (ROT_ / 2)) return;
    int j  = idx & 15;
    int s  = (idx >> 4) & (S_ - 1);
    int bh = idx >> 15;

    float inv = powf(10000.0f, -((float)j) / 16.0f);
    float ang = (float)s * inv;
    float c  = cosf(ang);
    float sn = sinf(ang);

    size_t base = ((size_t)bh * S_ + s) * HS_;
    __half* qp = &g_Qh[base];
    __half* kp = &g_Kh[base];

    float q0 = __half2float(qp[j]), q1 = __half2float(qp[j + 16]);
    qp[j]      = __float2half_rn(q0 * c - q1 * sn);
    qp[j + 16] = __float2half_rn(q1 * c + q0 * sn);

    float k0 = __half2float(kp[j]), k1 = __half2float(kp[j + 16]);
    kp[j]      = __float2half_rn(k0 * c - k1 * sn);
    kp[j + 16] = __float2half_rn(k1 * c + k0 * sn);
}

// ---------------------------------------------------------------------------
// Flash attention v4: register-resident P (FA2 style), ONE barrier per tile.
//  - S phase: warp w owns q-rows [16w,16w+16); S accums stay in registers.
//  - P packed to half2 A-frags directly (c-layout == a-layout), no P smem.
//  - PV: same warp multiplies its 16 rows by V^T (d=128 as n-dim): 64 mma.
//  - K and V double-buffered; prefetch issued right after the single barrier.
// Smem (halfs): Q 128x136 | K0,K1 64x136 | V0,V1 128x72  = 106496 bytes.
// 2 CTAs/SM (213 KB), launch_bounds(256,2).
// ---------------------------------------------------------------------------
#define FQ 128
#define FKV 64
#define QSTRH 136
#define VSTRH 72
#define F4_Q  0
#define F4_K0 (FQ * QSTRH)                // 17408
#define F4_K1 (F4_K0 + FKV * QSTRH)       // 26112
#define F4_V0 (F4_K1 + FKV * QSTRH)       // 34816
#define F4_V1 (F4_V0 + HS_ * VSTRH)       // 44032
#define FLASH_SMEM ((F4_V1 + HS_ * VSTRH) * 2)   // 106496 bytes
#define KBUF_B (FKV * QSTRH * 2)          // 17408 bytes per K buffer
#define VBUF_B (HS_ * VSTRH * 2)          // 18432 bytes per V buffer

__global__ __launch_bounds__(256, 2) void flash4_kernel()
{
    extern __shared__ char smc[];
    const uint32_t sQ  = smem_to_u32(smc);
    const uint32_t sK0 = sQ + F4_K0 * 2;
    const uint32_t sV0 = sQ + F4_V0 * 2;

    const int tid  = threadIdx.x;
    const int wid  = tid >> 5;
    const int lane = tid & 31;
    const int g = lane >> 2, q = lane & 3;
    const int bh = blockIdx.y;
    const int qt = gridDim.x - 1 - blockIdx.x;
    const int qBase = qt * FQ;

    const __half* Qg  = g_Qh + ((size_t)bh * S_ + qBase) * HS_;
    const __half* Kg  = g_Kh + (size_t)bh * S_ * HS_;
    const __half* Vtg = g_Vt + (size_t)bh * HS_ * S_;

    // ldmatrix lane-address offsets (bytes)
    const uint32_t qOff =
        (uint32_t)(((wid * 16 + (lane & 15)) * QSTRH + (lane >> 4) * 8) * 2);
    uint32_t kOff[4];
    {
        int bk = ((lane >> 3) & 1) * 8;
        int bn = ((lane >> 4) * 8) + (lane & 7);
        #pragma unroll
        for (int j = 0; j < 4; j++)
            kOff[j] = (uint32_t)(((j * 16 + bn) * QSTRH + bk) * 2);
    }
    uint32_t vOff[8];
    {
        int bk = ((lane >> 3) & 1) * 8;
        int bn = ((lane >> 4) * 8) + (lane & 7);
        #pragma unroll
        for (int j = 0; j < 8; j++)
            vOff[j] = (uint32_t)(((j * 16 + bn) * VSTRH + bk) * 2);
    }

    // prologue: Q (128x256B) + K(0) (64x256B) + V^T(0) (128x128B)
    #pragma unroll
    for (int i = 0; i < 8; i++) {
        int f4 = i * 256 + tid;
        int r = f4 >> 4, c = f4 & 15;
        cp_async16(sQ + r * (QSTRH * 2) + c * 16, Qg + r * HS_ + c * 8);
    }
    #pragma unroll
    for (int i = 0; i < 4; i++) {
        int f4 = i * 256 + tid;
        int r = f4 >> 4, c = f4 & 15;
        cp_async16(sK0 + r * (QSTRH * 2) + c * 16, Kg + r * HS_ + c * 8);
    }
    #pragma unroll
    for (int i = 0; i < 4; i++) {
        int f4 = i * 256 + tid;
        int r = f4 >> 3, c = f4 & 7;
        cp_async16(sV0 + r * (VSTRH * 2) + c * 16, Vtg + (size_t)r * S_ + c * 8);
    }
    CP_COMMIT();

    float m0 = -1e30f, m1 = -1e30f, l0 = 0.f, l1 = 0.f;
    float o[16][4];
    #pragma unroll
    for (int nt = 0; nt < 16; nt++)
        #pragma unroll
        for (int r = 0; r < 4; r++) o[nt][r] = 0.f;

    const int srow0 = wid * 16 + g;
    const int ntiles = 2 * qt + 2;
    int kbuf = 0;

    for (int t = 0; t < ntiles; t++) {
        cp_wait<0>();
        __syncthreads();          // K(t)/V(t) visible; all warps done with t-1 bufs

        // prefetch K(t+1), V(t+1) into alternate buffers — covered by compute
        if (t + 1 < ntiles) {
            uint32_t sKn = sK0 + (kbuf ^ 1) * KBUF_B;
            uint32_t sVn = sV0 + (kbuf ^ 1) * VBUF_B;
            const __half* Kt = Kg + (size_t)(t + 1) * FKV * HS_;
            #pragma unroll
            for (int i = 0; i < 4; i++) {
                int f4 = i * 256 + tid;
                int r = f4 >> 4, c = f4 & 15;
                cp_async16(sKn + r * (QSTRH * 2) + c * 16, Kt + r * HS_ + c * 8);
            }
            #pragma unroll
            for (int i = 0; i < 4; i++) {
                int f4 = i * 256 + tid;
                int r = f4 >> 3, c = f4 & 7;
                cp_async16(sVn + r * (VSTRH * 2) + c * 16,
                           Vtg + (size_t)r * S_ + (t + 1) * FKV + c * 8);
            }
            CP_COMMIT();
        }

        const uint32_t sKb = sK0 + kbuf * KBUF_B;
        const uint32_t sVb = sV0 + kbuf * VBUF_B;

        // ---- S = Q K^T via ldmatrix ----
        float s[8][4];
        #pragma unroll
        for (int nt = 0; nt < 8; nt++)
            #pragma unroll
            for (int r = 0; r < 4; r++) s[nt][r] = 0.f;

        #pragma unroll
        for (int kk = 0; kk < 8; kk++) {
            uint32_t kadd = kk * 32;
            uint32_t a[4];
            ldsm_x4(a, sQ + qOff + kadd);
            #pragma unroll
            for (int j = 0; j < 4; j++) {
                uint32_t bq[4];
                ldsm_x4(bq, sKb + kOff[j] + kadd);
                mma_f16(s[2 * j],     a, &bq[0]);
                mma_f16(s[2 * j + 1], a, &bq[2]);
            }
        }

        // ---- causal mask (diagonal tiles) ----
        if (t >= 2 * qt) {
            int r0 = qBase + srow0, r1 = r0 + 8;
            #pragma unroll
            for (int nt = 0; nt < 8; nt++) {
                int c0 = t * FKV + nt * 8 + 2 * q;
                if (c0     > r0) s[nt][0] = -1e30f;
                if (c0 + 1 > r0) s[nt][1] = -1e30f;
                if (c0     > r1) s[nt][2] = -1e30f;
                if (c0 + 1 > r1) s[nt][3] = -1e30f;
            }
        }

        // ---- online softmax (rows srow0, srow0+8; quad reduce); P -> regs ----
        float rm0 = -1e30f, rm1 = -1e30f;
        #pragma unroll
        for (int nt = 0; nt < 8; nt++) {
            rm0 = fmaxf(rm0, fmaxf(s[nt][0], s[nt][1]));
            rm1 = fmaxf(rm1, fmaxf(s[nt][2], s[nt][3]));
        }
        rm0 = fmaxf(rm0, __shfl_xor_sync(0xffffffffu, rm0, 1));
        rm0 = fmaxf(rm0, __shfl_xor_sync(0xffffffffu, rm0, 2));
        rm1 = fmaxf(rm1, __shfl_xor_sync(0xffffffffu, rm1, 1));
        rm1 = fmaxf(rm1, __shfl_xor_sync(0xffffffffu, rm1, 2));
        float mn0 = fmaxf(m0, rm0), mn1 = fmaxf(m1, rm1);
        float al0 = __expf(m0 - mn0), al1 = __expf(m1 - mn1);
        float rs0 = 0.f, rs1 = 0.f;
        uint32_t ph[16];          // A-frags: ph[2nt]=(rows g), ph[2nt+1]=(rows g+8)
        #pragma unroll
        for (int nt = 0; nt < 8; nt++) {
            float p0 = __expf(s[nt][0] - mn0);
            float p1 = __expf(s[nt][1] - mn0);
            float p2 = __expf(s[nt][2] - mn1);
            float p3 = __expf(s[nt][3] - mn1);
            rs0 += p0 + p1;
            rs1 += p2 + p3;
            __half2 hA = __floats2half2_rn(p0, p1);
            __half2 hB = __floats2half2_rn(p2, p3);
            ph[2 * nt]     = *(uint32_t*)&hA;
            ph[2 * nt + 1] = *(uint32_t*)&hB;
        }
        rs0 += __shfl_xor_sync(0xffffffffu, rs0, 1);
        rs0 += __shfl_xor_sync(0xffffffffu, rs0, 2);
        rs1 += __shfl_xor_sync(0xffffffffu, rs1, 1);
        rs1 += __shfl_xor_sync(0xffffffffu, rs1, 2);
        l0 = l0 * al0 + rs0;
        l1 = l1 * al1 + rs1;
        m0 = mn0; m1 = mn1;

        // ---- O rescale + O += P V (register P; no barrier needed) ----
        #pragma unroll
        for (int nt = 0; nt < 16; nt++) {
            o[nt][0] *= al0; o[nt][1] *= al0;
            o[nt][2] *= al1; o[nt][3] *= al1;
        }
        #pragma unroll
        for (int kk = 0; kk < 4; kk++) {
            uint32_t kadd = kk * 32;
            const uint32_t* a = &ph[4 * kk];   // a0..a3 for this k16 step
            #pragma unroll
            for (int j = 0; j < 8; j++) {
                uint32_t bv[4];
                ldsm_x4(bv, sVb + vOff[j] + kadd);
                mma_f16(o[2 * j],     a, &bv[0]);
                mma_f16(o[2 * j + 1], a, &bv[2]);
            }
        }

        kbuf ^= 1;
    }

    // ---- writeout: normalize (register l), RN to half, store g_Yh [B,S,E] ----
    float i0 = 1.f / l0, i1 = 1.f / l1;
    int b = bh >> 4, h = bh & 15;
    __half* Y0 = g_Yh + ((size_t)b * S_ + qBase + srow0) * E_ + h * HS_;
    __half* Y1 = Y0 + 8 * E_;
    #pragma unroll
    for (int nt = 0; nt < 16; nt++) {
        int c0 = nt * 8 + 2 * q;
        *(__half2*)&Y0[c0] = __floats2half2_rn(o[nt][0] * i0, o[nt][1] * i0);
        *(__half2*)&Y1[c0] = __floats2half2_rn(o[nt][2] * i1, o[nt][3] * i1);
    }
}

// ---------------------------------------------------------------------------
// Launch
// ---------------------------------------------------------------------------
extern "C" void kernel_launch(void* const* d_in, const int* in_sizes, int n_in,
                              void* d_out, int out_size)
{
    const float* x       = (const float*)d_in[0];
    const float* w_qkv   = (const float*)d_in[1];
    const float* b_qkv   = (const float*)d_in[2];
    const float* w_dense = (const float*)d_in[3];
    const float* b_dense = (const float*)d_in[4];
    float* out = (float*)d_out;

    cudaFuncSetAttribute(mma_gemm<0>, cudaFuncAttributeMaxDynamicSharedMemorySize, GEMM_SMEM);
    cudaFuncSetAttribute(mma_gemm<1>, cudaFuncAttributeMaxDynamicSharedMemorySize, GEMM_SMEM);
    cudaFuncSetAttribute(flash4_kernel, cudaFuncAttributeMaxDynamicSharedMemorySize, FLASH_SMEM);

    // 0. Convert all GEMM inputs to fp16 (RN) in one launch
    convert_all_kernel<<<(N8_ALL + 255) / 256, 256>>>(x, w_qkv, w_dense);

    // 1. QKV projection + bias -> Qh (scaled) / Kh / V^T (all fp16)
    mma_gemm<0><<<dim3(NQKV / 128, M_ / 128), 256, GEMM_SMEM>>>(b_qkv, nullptr);

    // 2. RoPE on first 32 dims of Q and K
    rope_kernel<<<(B_ * H_ * S_ * (ROT_ / 2)) / 256, 256>>>();

    // 3. Causal flash attention (register-P FA2, 2 CTA/SM) -> g_Yh
    flash4_kernel<<<dim3(S_ / FQ, B_ * H_), 256, FLASH_SMEM>>>();

    // 4. Dense projection + bias -> fp32 output
    mma_gemm<1><<<dim3(E_ / 128, M_ / 128), 256, GEMM_SMEM>>>(b_dense, out);
}